// round 2
// baseline (speedup 1.0000x reference)
#include <cuda_runtime.h>
#include <math.h>

// Problem shape (fixed by the reference).
#define BB   2
#define HH   16
#define SS   2048
#define DD   64
#define TILE 64
#define NT   (SS / TILE)   // 32 tiles per sequence

// Per-row softmax stats (written by kernel A, read by kernel B).
__device__ float g_m[BB * HH * SS];
__device__ float g_l[BB * HH * SS];
// Fallback scratch for raw scores if the harness output only holds `out`.
__device__ float g_scores[(size_t)BB * HH * SS * SS];

// ---------------------------------------------------------------------------
// Kernel A: raw scores (causal-masked, scaled) -> attn buffer, plus online
// per-row (max, sumexp) statistics.
// Block = 256 threads, one (b*h, q-tile) pair per block.
// ---------------------------------------------------------------------------
__global__ void __launch_bounds__(256) attn_scores_kernel(
    const float* __restrict__ q,
    const float* __restrict__ k,
    float* __restrict__ attn)
{
    const int bh = blockIdx.y;
    const int qt = blockIdx.x;
    const int q0 = qt * TILE;
    const int tid = threadIdx.x;
    const int tx = tid & 15;   // j-group (key cols)
    const int ty = tid >> 4;   // i-group (query rows)

    __shared__ __align__(16) float Qt[TILE * 68];  // [d][i], padded
    __shared__ __align__(16) float Kt[TILE * 68];  // [d][j], padded
    __shared__ float m_row[TILE];
    __shared__ float l_row[TILE];

    const float* qb = q + ((size_t)bh * SS + q0) * DD;
    const float* kb = k + (size_t)bh * SS * DD;
    float* ab = attn + ((size_t)bh * SS + q0) * SS;

    // Load Q tile transposed: Qt[d][i]
    for (int idx = tid; idx < TILE * DD; idx += 256) {
        int i = idx >> 6, d = idx & 63;
        Qt[d * 68 + i] = qb[idx];
    }
    if (tid < TILE) { m_row[tid] = -INFINITY; l_row[tid] = 0.f; }
    __syncthreads();

    const float scale = 0.125f;  // 1/sqrt(64)

    for (int kt = 0; kt <= qt; ++kt) {
        const float* kp = kb + (size_t)kt * TILE * DD;
        for (int idx = tid; idx < TILE * DD; idx += 256) {
            int j = idx >> 6, d = idx & 63;
            Kt[d * 68 + j] = kp[idx];
        }
        __syncthreads();

        float acc[4][4] = {};
        #pragma unroll 16
        for (int d = 0; d < DD; ++d) {
            float4 a = *(const float4*)&Qt[d * 68 + ty * 4];
            float4 b = *(const float4*)&Kt[d * 68 + tx * 4];
            float av[4] = {a.x, a.y, a.z, a.w};
            float bv[4] = {b.x, b.y, b.z, b.w};
            #pragma unroll
            for (int ii = 0; ii < 4; ++ii)
                #pragma unroll
                for (int jj = 0; jj < 4; ++jj)
                    acc[ii][jj] = fmaf(av[ii], bv[jj], acc[ii][jj]);
        }

        const int rbase = q0 + ty * 4;
        const int cbase = kt * TILE + tx * 4;
        #pragma unroll
        for (int ii = 0; ii < 4; ++ii)
            #pragma unroll
            for (int jj = 0; jj < 4; ++jj) {
                float s = acc[ii][jj] * scale;
                if (cbase + jj > rbase + ii) s = -INFINITY;  // causal
                acc[ii][jj] = s;
            }

        // Write raw scores (re-read once by kernel B; stream past L2).
        #pragma unroll
        for (int ii = 0; ii < 4; ++ii) {
            float4 s4 = make_float4(acc[ii][0], acc[ii][1], acc[ii][2], acc[ii][3]);
            __stcs((float4*)&ab[(size_t)(ty * 4 + ii) * SS + cbase], s4);
        }

        // Online (m, l) update per row.
        #pragma unroll
        for (int ii = 0; ii < 4; ++ii) {
            float m_t = fmaxf(fmaxf(acc[ii][0], acc[ii][1]),
                              fmaxf(acc[ii][2], acc[ii][3]));
            float l_t = 0.f;
            if (m_t > -INFINITY) {
                l_t = __expf(acc[ii][0] - m_t) + __expf(acc[ii][1] - m_t)
                    + __expf(acc[ii][2] - m_t) + __expf(acc[ii][3] - m_t);
            }
            // Reduce over the 16 tx lanes (contiguous lanes within half-warp).
            #pragma unroll
            for (int off = 1; off < 16; off <<= 1) {
                float m_o = __shfl_xor_sync(0xffffffffu, m_t, off);
                float l_o = __shfl_xor_sync(0xffffffffu, l_t, off);
                float m_n = fmaxf(m_t, m_o);
                float l_n = (m_n == -INFINITY)
                              ? 0.f
                              : (l_t * __expf(m_t - m_n) + l_o * __expf(m_o - m_n));
                m_t = m_n; l_t = l_n;
            }
            if (tx == 0) {  // single owner per row across the whole k-loop
                int r = ty * 4 + ii;
                float m_old = m_row[r], l_old = l_row[r];
                float m_n = fmaxf(m_old, m_t);
                float l_n = (m_n == -INFINITY)
                              ? 0.f
                              : (l_old * __expf(m_old - m_n) + l_t * __expf(m_t - m_n));
                m_row[r] = m_n; l_row[r] = l_n;
            }
        }
        __syncthreads();
    }

    if (tid < TILE) {
        g_m[(size_t)bh * SS + q0 + tid] = m_row[tid];
        g_l[(size_t)bh * SS + q0 + tid] = l_row[tid];
    }
}

// ---------------------------------------------------------------------------
// Kernel B: normalize attn in place (p = exp(s-m)/l), zero-fill the
// above-diagonal tiles, and compute out = P @ V.
// ---------------------------------------------------------------------------
__global__ void __launch_bounds__(256) attn_pv_kernel(
    const float* __restrict__ v,
    float* __restrict__ attn,
    float* __restrict__ out)
{
    const int bh = blockIdx.y;
    const int qt = blockIdx.x;
    const int q0 = qt * TILE;
    const int tid = threadIdx.x;
    const int tx = tid & 15;   // d-group
    const int ty = tid >> 4;   // i-group

    __shared__ __align__(16) float Ps[TILE * 68];  // [i][k], row-major padded
    __shared__ __align__(16) float Vs[TILE * 68];  // [k][d], row-major padded
    __shared__ float m_row[TILE];
    __shared__ float il_row[TILE];

    float* ab = attn + ((size_t)bh * SS + q0) * SS;
    const float* vb = v + (size_t)bh * SS * DD;

    if (tid < TILE) {
        size_t ridx = (size_t)bh * SS + q0 + tid;
        m_row[tid] = g_m[ridx];
        il_row[tid] = 1.0f / g_l[ridx];
    }
    __syncthreads();

    float acc[4][4] = {};

    for (int kt = 0; kt <= qt; ++kt) {
        const float* vp = vb + (size_t)kt * TILE * DD;
        for (int idx = tid; idx < TILE * DD; idx += 256) {
            int kk = idx >> 6, d = idx & 63;
            Vs[kk * 68 + d] = vp[idx];
        }
        // Read raw scores (read-once), normalize, write final attn (write-once,
        // never re-read), stage P in smem.
        for (int idx4 = tid; idx4 < TILE * 16; idx4 += 256) {
            int r = idx4 >> 4;
            int c = (idx4 & 15) * 4;
            float* gp = &ab[(size_t)r * SS + kt * TILE + c];
            float4 s = __ldcs((const float4*)gp);
            float m = m_row[r], il = il_row[r];
            float4 p;
            p.x = __expf(s.x - m) * il;
            p.y = __expf(s.y - m) * il;
            p.z = __expf(s.z - m) * il;
            p.w = __expf(s.w - m) * il;
            __stcs((float4*)gp, p);
            *(float4*)&Ps[r * 68 + c] = p;
        }
        __syncthreads();

        #pragma unroll 16
        for (int kk = 0; kk < TILE; ++kk) {
            // P column via broadcast scalar LDS (conflict-free: same addr per 16-lane group)
            float a0 = Ps[(ty * 4 + 0) * 68 + kk];
            float a1 = Ps[(ty * 4 + 1) * 68 + kk];
            float a2 = Ps[(ty * 4 + 2) * 68 + kk];
            float a3 = Ps[(ty * 4 + 3) * 68 + kk];
            float4 b = *(const float4*)&Vs[kk * 68 + tx * 4];
            float bv[4] = {b.x, b.y, b.z, b.w};
            float av[4] = {a0, a1, a2, a3};
            #pragma unroll
            for (int ii = 0; ii < 4; ++ii)
                #pragma unroll
                for (int jj = 0; jj < 4; ++jj)
                    acc[ii][jj] = fmaf(av[ii], bv[jj], acc[ii][jj]);
        }
        __syncthreads();
    }

    // Zero-fill strictly-above-diagonal tiles (d_out is poisoned 0xAA).
    const float4 z = make_float4(0.f, 0.f, 0.f, 0.f);
    for (int kt = qt + 1; kt < NT; ++kt) {
        for (int idx4 = tid; idx4 < TILE * 16; idx4 += 256) {
            int r = idx4 >> 4;
            int c = (idx4 & 15) * 4;
            __stcs((float4*)&ab[(size_t)r * SS + kt * TILE + c], z);
        }
    }

    // Write out tile.
    float* ob = out + ((size_t)bh * SS + q0) * DD;
    #pragma unroll
    for (int ii = 0; ii < 4; ++ii) {
        float4 o = make_float4(acc[ii][0], acc[ii][1], acc[ii][2], acc[ii][3]);
        *(float4*)&ob[(size_t)(ty * 4 + ii) * DD + tx * 4] = o;
    }
}

// ---------------------------------------------------------------------------
// Launch: inputs are q, k, v, mask (mask is the deterministic causal tril,
// applied analytically). Output layout assumed [out | attn] per reference
// return order; falls back to device scratch if out_size only covers `out`.
// ---------------------------------------------------------------------------
extern "C" void kernel_launch(void* const* d_in, const int* in_sizes, int n_in,
                              void* d_out, int out_size)
{
    const float* q = (const float*)d_in[0];
    const float* k = (const float*)d_in[1];
    const float* v = (const float*)d_in[2];
    float* out = (float*)d_out;

    const size_t out_elems  = (size_t)BB * HH * SS * DD;   //   4,194,304
    const size_t attn_elems = (size_t)BB * HH * SS * SS;   // 134,217,728

    float* attn;
    if ((size_t)out_size >= out_elems + attn_elems) {
        attn = out + out_elems;
    } else {
        void* p = nullptr;
        cudaGetSymbolAddress(&p, g_scores);
        attn = (float*)p;
    }

    dim3 grid(NT, BB * HH);
    dim3 block(256);
    attn_scores_kernel<<<grid, block>>>(q, k, attn);
    attn_pv_kernel<<<grid, block>>>(v, attn, out);
}

// round 5
// speedup vs baseline: 1.1992x; 1.1992x over previous
#include <cuda_runtime.h>
#include <math.h>
#include <stdint.h>

// Problem shape (fixed by the reference).
#define BB   2
#define HH   16
#define SS   2048
#define DD   64
#define TILE 64
#define NT   (SS / TILE)   // 32 tiles per sequence

#define PAD  68            // smem row stride (floats); 68*4B = 272B, 16B-aligned

// Per-row softmax stats (written by kernel A, read by kernel B).
__device__ float g_m[BB * HH * SS];
__device__ float g_l[BB * HH * SS];
// Fallback scratch for raw scores if the harness output only holds `out`.
__device__ float g_scores[(size_t)BB * HH * SS * SS];

// ---- packed f32x2 helpers (sm_103a: ptxas never auto-fuses; PTX only) ----
#define PACK2(dst, x, y) \
    asm("mov.b64 %0, {%1, %2};" : "=l"(dst) : "r"(__float_as_uint(x)), "r"(__float_as_uint(y)))
#define FMA2(acc, a, b) \
    asm("fma.rn.f32x2 %0, %1, %2, %3;" : "=l"(acc) : "l"(a), "l"(b), "l"(acc))
#define UNPK2(lo, hi, v) \
    asm("mov.b64 {%0, %1}, %2;" : "=r"(lo), "=r"(hi) : "l"(v))

// ---- cp.async helpers ----
__device__ __forceinline__ void cp16(uint32_t dst, const void* src) {
    asm volatile("cp.async.cg.shared.global [%0], [%1], 16;" :: "r"(dst), "l"(src));
}
__device__ __forceinline__ void cp_commit() { asm volatile("cp.async.commit_group;"); }
__device__ __forceinline__ void cp_wait1()  { asm volatile("cp.async.wait_group 1;"); }
__device__ __forceinline__ void cp_wait0()  { asm volatile("cp.async.wait_group 0;"); }

// ===========================================================================
// Kernel A: raw scores (causal-masked, scaled) -> attn buffer, plus per-row
// (max, sumexp) statistics held in registers (one reduce at the end).
// Thread (tx,ty) owns rows {ty+16*ii} and cols {tx+16*jj} of the 64x64 tile
// (strided ownership -> conflict-free LDS on the PAD=68 row-major layout).
// ===========================================================================
__global__ void __launch_bounds__(256) attn_scores_kernel(
    const float* __restrict__ q,
    const float* __restrict__ k,
    float* __restrict__ attn)
{
    extern __shared__ float sm[];
    float* Qs  = sm;                  // [i][d], stride PAD
    float* Ks0 = sm + TILE * PAD;     // [j][d], stride PAD (double-buffered)
    float* Ks1 = Ks0 + TILE * PAD;

    const int bh = blockIdx.y;
    const int qt = (NT - 1) - blockIdx.x;   // heavy-first
    const int q0 = qt * TILE;
    const int tid = threadIdx.x;
    const int tx = tid & 15, ty = tid >> 4;

    const float* qb = q + ((size_t)bh * SS + q0) * DD;
    const float* kb = k + (size_t)bh * SS * DD;
    float* ab = attn + ((size_t)bh * SS + q0) * SS;

    uint32_t ks_u[2];
    ks_u[0] = (uint32_t)__cvta_generic_to_shared(Ks0);
    ks_u[1] = (uint32_t)__cvta_generic_to_shared(Ks1);

    // Load Q tile (row-major, padded)
    {
        const float4* src = (const float4*)qb;
        for (int c = tid; c < TILE * 16; c += 256) {
            int i = c >> 4, cc = c & 15;
            *(float4*)&Qs[i * PAD + cc * 4] = src[i * 16 + cc];
        }
    }
    // Prefetch K tile 0
    {
        const float4* src = (const float4*)kb;
        for (int c = tid; c < TILE * 16; c += 256) {
            int j = c >> 4, cc = c & 15;
            cp16(ks_u[0] + (uint32_t)(j * PAD + cc * 4) * 4u, src + (j * 16 + cc));
        }
        cp_commit();
    }

    float m_r[4] = {-INFINITY, -INFINITY, -INFINITY, -INFINITY};
    float l_r[4] = {0.f, 0.f, 0.f, 0.f};

    for (int kt = 0; kt <= qt; ++kt) {
        const int buf = kt & 1;
        if (kt < qt) {
            const float4* src = (const float4*)(kb + (size_t)(kt + 1) * TILE * DD);
            for (int c = tid; c < TILE * 16; c += 256) {
                int j = c >> 4, cc = c & 15;
                cp16(ks_u[buf ^ 1] + (uint32_t)(j * PAD + cc * 4) * 4u, src + (j * 16 + cc));
            }
            cp_commit();
            cp_wait1();   // current tile's group done (newest may stay in flight)
        } else {
            cp_wait0();
        }
        __syncthreads();

        const float* Kb = buf ? Ks1 : Ks0;

        // QK^T with packed f32x2 (split accumulators over even/odd d).
        unsigned long long acc2[4][4];
        #pragma unroll
        for (int ii = 0; ii < 4; ++ii)
            #pragma unroll
            for (int jj = 0; jj < 4; ++jj) acc2[ii][jj] = 0ull;

        #pragma unroll 4
        for (int d = 0; d < DD; d += 4) {
            float4 qv[4], kv[4];
            #pragma unroll
            for (int ii = 0; ii < 4; ++ii)
                qv[ii] = *(const float4*)&Qs[(ty + 16 * ii) * PAD + d];
            #pragma unroll
            for (int jj = 0; jj < 4; ++jj)
                kv[jj] = *(const float4*)&Kb[(tx + 16 * jj) * PAD + d];
            unsigned long long qp[4][2], kp[4][2];
            #pragma unroll
            for (int ii = 0; ii < 4; ++ii) {
                PACK2(qp[ii][0], qv[ii].x, qv[ii].y);
                PACK2(qp[ii][1], qv[ii].z, qv[ii].w);
            }
            #pragma unroll
            for (int jj = 0; jj < 4; ++jj) {
                PACK2(kp[jj][0], kv[jj].x, kv[jj].y);
                PACK2(kp[jj][1], kv[jj].z, kv[jj].w);
            }
            #pragma unroll
            for (int ii = 0; ii < 4; ++ii)
                #pragma unroll
                for (int jj = 0; jj < 4; ++jj) {
                    FMA2(acc2[ii][jj], qp[ii][0], kp[jj][0]);
                    FMA2(acc2[ii][jj], qp[ii][1], kp[jj][1]);
                }
        }

        // Fold halves, scale, mask, store raw scores, update register (m,l).
        #pragma unroll
        for (int ii = 0; ii < 4; ++ii) {
            const int rloc = ty + 16 * ii;
            const int row  = q0 + rloc;
            float s[4];
            #pragma unroll
            for (int jj = 0; jj < 4; ++jj) {
                uint32_t lo, hi; UNPK2(lo, hi, acc2[ii][jj]);
                float val = (__uint_as_float(lo) + __uint_as_float(hi)) * 0.125f;
                int col = kt * TILE + tx + 16 * jj;
                if (col > row) val = -INFINITY;   // causal
                s[jj] = val;
                __stcs(&ab[(size_t)rloc * SS + col], val);
            }
            float mt = fmaxf(fmaxf(s[0], s[1]), fmaxf(s[2], s[3]));
            float mn = fmaxf(m_r[ii], mt);
            if (mn != -INFINITY) {
                l_r[ii] = l_r[ii] * __expf(m_r[ii] - mn)
                        + __expf(s[0] - mn) + __expf(s[1] - mn)
                        + __expf(s[2] - mn) + __expf(s[3] - mn);
                m_r[ii] = mn;
            }
        }
        __syncthreads();   // FMA reads of Kb done before next prefetch overwrites it
    }

    // One cross-lane reduce over the 16 tx lanes that share each row.
    #pragma unroll
    for (int ii = 0; ii < 4; ++ii) {
        float m1 = m_r[ii], l1 = l_r[ii];
        #pragma unroll
        for (int off = 1; off < 16; off <<= 1) {
            float m2 = __shfl_xor_sync(0xffffffffu, m1, off);
            float l2 = __shfl_xor_sync(0xffffffffu, l1, off);
            float mn = fmaxf(m1, m2);
            float ln = (mn == -INFINITY) ? 0.f
                       : (l1 * __expf(m1 - mn) + l2 * __expf(m2 - mn));
            m1 = mn; l1 = ln;
        }
        if (tx == 0) {
            g_m[(size_t)bh * SS + q0 + ty + 16 * ii] = m1;
            g_l[(size_t)bh * SS + q0 + ty + 16 * ii] = l1;
        }
    }
}

// ===========================================================================
// Kernel B: normalize attn in place (p = exp(s-m)/l, via cp.async-staged smem
// tiles), zero-fill above-diagonal tiles, compute out = P @ V with f32x2.
// ===========================================================================
__global__ void __launch_bounds__(256) attn_pv_kernel(
    const float* __restrict__ v,
    float* __restrict__ attn,
    float* __restrict__ out)
{
    extern __shared__ float sm[];
    float* Ss0 = sm;                     // score/P tile, [r][c] stride PAD
    float* Ss1 = Ss0 + TILE * PAD;
    float* Vs0 = Ss1 + TILE * PAD;       // V tile, [k][d] stride PAD
    float* Vs1 = Vs0 + TILE * PAD;
    float* m_row  = Vs1 + TILE * PAD;    // 64
    float* il_row = m_row + TILE;        // 64

    const int bh = blockIdx.y;
    const int qt = (NT - 1) - blockIdx.x;   // heavy-first
    const int q0 = qt * TILE;
    const int tid = threadIdx.x;
    const int tx = tid & 15, ty = tid >> 4;

    float* ab = attn + ((size_t)bh * SS + q0) * SS;
    const float* vb = v + (size_t)bh * SS * DD;

    uint32_t ss_u[2], vs_u[2];
    ss_u[0] = (uint32_t)__cvta_generic_to_shared(Ss0);
    ss_u[1] = (uint32_t)__cvta_generic_to_shared(Ss1);
    vs_u[0] = (uint32_t)__cvta_generic_to_shared(Vs0);
    vs_u[1] = (uint32_t)__cvta_generic_to_shared(Vs1);

    if (tid < TILE) {
        size_t ridx = (size_t)bh * SS + q0 + tid;
        m_row[tid]  = g_m[ridx];
        il_row[tid] = 1.0f / g_l[ridx];
    }

    // Prefetch tile 0 (scores + V) as one group.
    {
        const float4* srcS = (const float4*)ab;       // +r*512 + cc
        const float4* srcV = (const float4*)vb;       // +j*16 + cc
        for (int c = tid; c < TILE * 16; c += 256) {
            int r = c >> 4, cc = c & 15;
            cp16(ss_u[0] + (uint32_t)(r * PAD + cc * 4) * 4u, srcS + ((size_t)r * (SS / 4) + cc));
            cp16(vs_u[0] + (uint32_t)(r * PAD + cc * 4) * 4u, srcV + (r * 16 + cc));
        }
        cp_commit();
    }

    unsigned long long acc2[4][2];
    #pragma unroll
    for (int ii = 0; ii < 4; ++ii) { acc2[ii][0] = 0ull; acc2[ii][1] = 0ull; }

    for (int kt = 0; kt <= qt; ++kt) {
        const int buf = kt & 1;
        if (kt < qt) {
            const float4* srcS = (const float4*)(ab + (size_t)(kt + 1) * TILE);
            const float4* srcV = (const float4*)(vb + (size_t)(kt + 1) * TILE * DD);
            for (int c = tid; c < TILE * 16; c += 256) {
                int r = c >> 4, cc = c & 15;
                cp16(ss_u[buf ^ 1] + (uint32_t)(r * PAD + cc * 4) * 4u, srcS + ((size_t)r * (SS / 4) + cc));
                cp16(vs_u[buf ^ 1] + (uint32_t)(r * PAD + cc * 4) * 4u, srcV + (r * 16 + cc));
            }
            cp_commit();
            cp_wait1();
        } else {
            cp_wait0();
        }
        __syncthreads();

        float* Sb = buf ? Ss1 : Ss0;
        const float* Vb = buf ? Vs1 : Vs0;

        // Normalize in place: raw s -> p; also write final attn to gmem.
        for (int c = tid; c < TILE * 16; c += 256) {
            int r = c >> 4, cc = c & 15;
            float4 s4 = *(float4*)&Sb[r * PAD + cc * 4];
            float m = m_row[r], il = il_row[r];
            float4 p;
            p.x = __expf(s4.x - m) * il;
            p.y = __expf(s4.y - m) * il;
            p.z = __expf(s4.z - m) * il;
            p.w = __expf(s4.w - m) * il;
            *(float4*)&Sb[r * PAD + cc * 4] = p;
            __stcs((float4*)&ab[(size_t)r * SS + kt * TILE + cc * 4], p);
        }
        __syncthreads();

        // out-tile FMA: acc[i][d] += P[i][kk] * V[kk][d], packed over d pairs.
        #pragma unroll 8
        for (int kk = 0; kk < TILE; ++kk) {
            float4 vv = *(const float4*)&Vb[kk * PAD + tx * 4];
            unsigned long long v01, v23;
            PACK2(v01, vv.x, vv.y);
            PACK2(v23, vv.z, vv.w);
            #pragma unroll
            for (int ii = 0; ii < 4; ++ii) {
                float p = Sb[(ty + 16 * ii) * PAD + kk];   // broadcast across tx
                unsigned long long pp; PACK2(pp, p, p);
                FMA2(acc2[ii][0], pp, v01);
                FMA2(acc2[ii][1], pp, v23);
            }
        }
        __syncthreads();   // reads of Sb/Vb done before next prefetch overwrites
    }

    // Zero-fill strictly-above-diagonal tiles (d_out poisoned 0xAA).
    const float4 z = make_float4(0.f, 0.f, 0.f, 0.f);
    for (int zt = qt + 1; zt < NT; ++zt) {
        for (int c = tid; c < TILE * 16; c += 256) {
            int r = c >> 4, cc = c & 15;
            __stcs((float4*)&ab[(size_t)r * SS + zt * TILE + cc * 4], z);
        }
    }

    // Write out tile.
    float* ob = out + ((size_t)bh * SS + q0) * DD;
    #pragma unroll
    for (int ii = 0; ii < 4; ++ii) {
        uint32_t lo, hi;
        float o0, o1, o2, o3;
        UNPK2(lo, hi, acc2[ii][0]); o0 = __uint_as_float(lo); o1 = __uint_as_float(hi);
        UNPK2(lo, hi, acc2[ii][1]); o2 = __uint_as_float(lo); o3 = __uint_as_float(hi);
        *(float4*)&ob[(size_t)(ty + 16 * ii) * DD + tx * 4] = make_float4(o0, o1, o2, o3);
    }
}

// ---------------------------------------------------------------------------
// Launch. Inputs: q, k, v, mask (mask is the deterministic causal tril,
// applied analytically). Output layout [out | attn] per reference return
// order (validated in round 2); device-scratch fallback kept.
// ---------------------------------------------------------------------------
extern "C" void kernel_launch(void* const* d_in, const int* in_sizes, int n_in,
                              void* d_out, int out_size)
{
    const float* q = (const float*)d_in[0];
    const float* k = (const float*)d_in[1];
    const float* v = (const float*)d_in[2];
    float* out = (float*)d_out;

    const size_t out_elems  = (size_t)BB * HH * SS * DD;
    const size_t attn_elems = (size_t)BB * HH * SS * SS;

    float* attn;
    if ((size_t)out_size >= out_elems + attn_elems) {
        attn = out + out_elems;
    } else {
        void* p = nullptr;
        cudaGetSymbolAddress(&p, g_scores);
        attn = (float*)p;
    }

    const int A_SMEM = 3 * TILE * PAD * 4;                 // 52224 B
    const int B_SMEM = 4 * TILE * PAD * 4 + 2 * TILE * 4;  // 70144 B
    cudaFuncSetAttribute(attn_scores_kernel,
                         cudaFuncAttributeMaxDynamicSharedMemorySize, A_SMEM);
    cudaFuncSetAttribute(attn_pv_kernel,
                         cudaFuncAttributeMaxDynamicSharedMemorySize, B_SMEM);

    dim3 grid(NT, BB * HH);
    dim3 block(256);
    attn_scores_kernel<<<grid, block, A_SMEM>>>(q, k, attn);
    attn_pv_kernel<<<grid, block, B_SMEM>>>(v, attn, out);
}